// round 2
// baseline (speedup 1.0000x reference)
#include <cuda_runtime.h>

#define NATOM 384
#define NB 8
#define KNBR 383
#define NT 4
#define M0 25
#define M1 50
#define M2 100
#define ET 40     // edges per tile
#define ER 8      // edges per thread (register block)
#define EG 5      // e-groups (ET/ER)
#define TPB 128

// Scratch (allocation-free rule: __device__ globals)
__device__ int g_perm[NATOM * KNBR];
__device__ int g_boff[NATOM * NT];

// Sort each atom's neighbor list by neighbor type (batch independent).
__global__ void prep_kernel(const int* __restrict__ types) {
    __shared__ int ts[NATOM];
    int t = threadIdx.x;
    ts[t] = types[t];
    __syncthreads();
    int cnt[NT] = {0, 0, 0, 0};
    for (int j = 0; j < NATOM; j++)
        if (j != t) cnt[ts[j]]++;
    int off[NT];
    off[0] = 0;
    for (int c = 1; c < NT; c++) off[c] = off[c - 1] + cnt[c - 1];
    for (int c = 0; c < NT; c++) g_boff[t * NT + c] = off[c];
    for (int j = 0; j < NATOM; j++)
        if (j != t) {
            int c = ts[j];
            g_perm[t * KNBR + off[c]++] = j;
        }
}

// Accurate fast tanh: (1-e)/(1+e), e = exp(-2|x|). ~1e-6 abs error.
__device__ __forceinline__ float tanh_f(float x) {
    float e = __expf(-2.0f * fabsf(x));
    float r = __fdividef(1.0f - e, 1.0f + e);
    return copysignf(r, x);
}

__global__ __launch_bounds__(TPB) void main_kernel(
    const float* __restrict__ coords, const int* __restrict__ types,
    const float* __restrict__ W0, const float* __restrict__ b0,
    const float* __restrict__ W1, const float* __restrict__ b1,
    const float* __restrict__ W2, const float* __restrict__ b2,
    float* __restrict__ out)
{
    __shared__ __align__(16) float W1s[M0 * M1];   // 1250
    __shared__ __align__(16) float W2s[M1 * M2];   // 5000
    __shared__ __align__(16) float W0s[M0];
    __shared__ __align__(16) float b0s[M0];
    __shared__ __align__(16) float b1s[M1];
    __shared__ __align__(16) float b2s[M2];
    __shared__ __align__(16) float h0s[M0 * ET];   // [i][e]
    __shared__ __align__(16) float h1s[M1 * ET];   // [o][e]
    __shared__ __align__(16) float aes[3 * ET];    // [c][e]
    __shared__ __align__(16) float Sred[EG][M2 * 3];
    __shared__ __align__(16) float Sfin[M2 * 3];

    int t = threadIdx.x;
    int bid = blockIdx.x;
    int n = bid % NATOM;
    int b = bid / NATOM;
    int tc = __ldg(&types[n]);
    float cx = __ldg(&coords[(b * NATOM + n) * 3 + 0]);
    float cy = __ldg(&coords[(b * NATOM + n) * 3 + 1]);
    float cz = __ldg(&coords[(b * NATOM + n) * 3 + 2]);

    int gm = t % 25;     // output group
    int ge = t / 25;     // edge group (0..4 for t<125)
    int e0 = ge * ER;

    float Sp[4][3];
#pragma unroll
    for (int q = 0; q < 4; q++) { Sp[q][0] = 0.f; Sp[q][1] = 0.f; Sp[q][2] = 0.f; }

    for (int tn = 0; tn < NT; tn++) {
        __syncthreads();   // smem weights free before reload
        int idx = tc * NT + tn;
        {
            const float4* src = (const float4*)(W2 + (size_t)idx * (M1 * M2));
            float4* dst = (float4*)W2s;
            for (int i = t; i < (M1 * M2) / 4; i += TPB) dst[i] = src[i];
        }
        for (int i = t; i < M0 * M1; i += TPB) W1s[i] = W1[(size_t)idx * (M0 * M1) + i];
        for (int i = t; i < M0; i += TPB) { W0s[i] = W0[idx * M0 + i]; b0s[i] = b0[idx * M0 + i]; }
        for (int i = t; i < M1; i += TPB) b1s[i] = b1[idx * M1 + i];
        for (int i = t; i < M2; i += TPB) b2s[i] = b2[idx * M2 + i];
        __syncthreads();

        int bs = g_boff[n * NT + tn];
        int be = (tn == NT - 1) ? KNBR : g_boff[n * NT + tn + 1];
        int cnt = be - bs;
        const int* pbase = g_perm + n * KNBR + bs;

        for (int t0 = 0; t0 < cnt; t0 += ET) {
            // ---- Stage 0: geometry + layer0 (threads 0..39) ----
            if (t < ET) {
                int e = t;
                int gi = t0 + e;
                float x = 0.f, ax = 0.f, ay = 0.f, az = 0.f;
                if (gi < cnt) {
                    int j = __ldg(&pbase[gi]);
                    float rx = cx - __ldg(&coords[(b * NATOM + j) * 3 + 0]);
                    float ry = cy - __ldg(&coords[(b * NATOM + j) * 3 + 1]);
                    float rz = cz - __ldg(&coords[(b * NATOM + j) * 3 + 2]);
                    float d2 = rx * rx + ry * ry + rz * rz;
                    x = rsqrtf(d2);
                    float i2 = x * x;
                    ax = rx * i2; ay = ry * i2; az = rz * i2;
                }
                aes[0 * ET + e] = ax;
                aes[1 * ET + e] = ay;
                aes[2 * ET + e] = az;
                if (gi < cnt) {
#pragma unroll 5
                    for (int i = 0; i < M0; i++)
                        h0s[i * ET + e] = tanh_f(fmaf(x, W0s[i], b0s[i]));
                } else {
#pragma unroll 5
                    for (int i = 0; i < M0; i++)
                        h0s[i * ET + e] = 0.f;
                }
            }
            __syncthreads();

            // ---- Stage 1: layer1 25->50 (125 threads, 2 out x 8 edges) ----
            if (t < 125) {
                float acc0[ER], acc1[ER];
                float bb0 = b1s[gm], bb1 = b1s[gm + 25];
#pragma unroll
                for (int e = 0; e < ER; e++) { acc0[e] = bb0; acc1[e] = bb1; }
#pragma unroll 5
                for (int j = 0; j < M0; j++) {
                    const float4* hp = (const float4*)(h0s + j * ET + e0);
                    float4 A = hp[0], Bv = hp[1];
                    float w0 = W1s[j * M1 + gm];
                    float w1 = W1s[j * M1 + gm + 25];
                    acc0[0] = fmaf(w0, A.x, acc0[0]); acc1[0] = fmaf(w1, A.x, acc1[0]);
                    acc0[1] = fmaf(w0, A.y, acc0[1]); acc1[1] = fmaf(w1, A.y, acc1[1]);
                    acc0[2] = fmaf(w0, A.z, acc0[2]); acc1[2] = fmaf(w1, A.z, acc1[2]);
                    acc0[3] = fmaf(w0, A.w, acc0[3]); acc1[3] = fmaf(w1, A.w, acc1[3]);
                    acc0[4] = fmaf(w0, Bv.x, acc0[4]); acc1[4] = fmaf(w1, Bv.x, acc1[4]);
                    acc0[5] = fmaf(w0, Bv.y, acc0[5]); acc1[5] = fmaf(w1, Bv.y, acc1[5]);
                    acc0[6] = fmaf(w0, Bv.z, acc0[6]); acc1[6] = fmaf(w1, Bv.z, acc1[6]);
                    acc0[7] = fmaf(w0, Bv.w, acc0[7]); acc1[7] = fmaf(w1, Bv.w, acc1[7]);
                }
#pragma unroll
                for (int e = 0; e < ER; e++) {
                    float h0v = h0s[gm * ET + e0 + e];
                    h1s[gm * ET + e0 + e] = tanh_f(acc0[e]) + h0v;
                    h1s[(gm + 25) * ET + e0 + e] = tanh_f(acc1[e]) + h0v;
                }
            }
            __syncthreads();

            // ---- Stage 2: layer2 50->100 + S accumulation ----
            if (t < 125) {
                float acc[4][ER];
#pragma unroll
                for (int q = 0; q < 4; q++) {
                    float bb = b2s[gm + 25 * q];
#pragma unroll
                    for (int e = 0; e < ER; e++) acc[q][e] = bb;
                }
#pragma unroll 5
                for (int j = 0; j < M1; j++) {
                    const float4* hp = (const float4*)(h1s + j * ET + e0);
                    float4 A = hp[0], Bv = hp[1];
                    float w0 = W2s[j * M2 + gm];
                    float w1 = W2s[j * M2 + gm + 25];
                    float w2v = W2s[j * M2 + gm + 50];
                    float w3 = W2s[j * M2 + gm + 75];
                    acc[0][0] = fmaf(w0, A.x, acc[0][0]); acc[1][0] = fmaf(w1, A.x, acc[1][0]);
                    acc[2][0] = fmaf(w2v, A.x, acc[2][0]); acc[3][0] = fmaf(w3, A.x, acc[3][0]);
                    acc[0][1] = fmaf(w0, A.y, acc[0][1]); acc[1][1] = fmaf(w1, A.y, acc[1][1]);
                    acc[2][1] = fmaf(w2v, A.y, acc[2][1]); acc[3][1] = fmaf(w3, A.y, acc[3][1]);
                    acc[0][2] = fmaf(w0, A.z, acc[0][2]); acc[1][2] = fmaf(w1, A.z, acc[1][2]);
                    acc[2][2] = fmaf(w2v, A.z, acc[2][2]); acc[3][2] = fmaf(w3, A.z, acc[3][2]);
                    acc[0][3] = fmaf(w0, A.w, acc[0][3]); acc[1][3] = fmaf(w1, A.w, acc[1][3]);
                    acc[2][3] = fmaf(w2v, A.w, acc[2][3]); acc[3][3] = fmaf(w3, A.w, acc[3][3]);
                    acc[0][4] = fmaf(w0, Bv.x, acc[0][4]); acc[1][4] = fmaf(w1, Bv.x, acc[1][4]);
                    acc[2][4] = fmaf(w2v, Bv.x, acc[2][4]); acc[3][4] = fmaf(w3, Bv.x, acc[3][4]);
                    acc[0][5] = fmaf(w0, Bv.y, acc[0][5]); acc[1][5] = fmaf(w1, Bv.y, acc[1][5]);
                    acc[2][5] = fmaf(w2v, Bv.y, acc[2][5]); acc[3][5] = fmaf(w3, Bv.y, acc[3][5]);
                    acc[0][6] = fmaf(w0, Bv.z, acc[0][6]); acc[1][6] = fmaf(w1, Bv.z, acc[1][6]);
                    acc[2][6] = fmaf(w2v, Bv.z, acc[2][6]); acc[3][6] = fmaf(w3, Bv.z, acc[3][6]);
                    acc[0][7] = fmaf(w0, Bv.w, acc[0][7]); acc[1][7] = fmaf(w1, Bv.w, acc[1][7]);
                    acc[2][7] = fmaf(w2v, Bv.w, acc[2][7]); acc[3][7] = fmaf(w3, Bv.w, acc[3][7]);
                }
                float r0[ER], r1[ER], a0[ER], a1[ER], a2[ER];
#pragma unroll
                for (int e = 0; e < ER; e++) {
                    r0[e] = h1s[gm * ET + e0 + e];
                    r1[e] = h1s[(gm + 25) * ET + e0 + e];
                    a0[e] = aes[0 * ET + e0 + e];
                    a1[e] = aes[1 * ET + e0 + e];
                    a2[e] = aes[2 * ET + e0 + e];
                }
#pragma unroll
                for (int q = 0; q < 4; q++) {
#pragma unroll
                    for (int e = 0; e < ER; e++) {
                        float res = (q & 1) ? r1[e] : r0[e];
                        float v = tanh_f(acc[q][e]) + res;
                        Sp[q][0] = fmaf(a0[e], v, Sp[q][0]);
                        Sp[q][1] = fmaf(a1[e], v, Sp[q][1]);
                        Sp[q][2] = fmaf(a2[e], v, Sp[q][2]);
                    }
                }
            }
            __syncthreads();
        }
    }

    // ---- Reduce S partials across edge groups ----
    if (t < 125) {
#pragma unroll
        for (int q = 0; q < 4; q++) {
            Sred[ge][(gm + 25 * q) * 3 + 0] = Sp[q][0];
            Sred[ge][(gm + 25 * q) * 3 + 1] = Sp[q][1];
            Sred[ge][(gm + 25 * q) * 3 + 2] = Sp[q][2];
        }
    }
    __syncthreads();
    if (t < M2) {
        float s0 = 0.f, s1 = 0.f, s2 = 0.f;
#pragma unroll
        for (int g = 0; g < EG; g++) {
            s0 += Sred[g][t * 3 + 0];
            s1 += Sred[g][t * 3 + 1];
            s2 += Sred[g][t * 3 + 2];
        }
        Sfin[t * 3 + 0] = s0; Sfin[t * 3 + 1] = s1; Sfin[t * 3 + 2] = s2;
    }
    __syncthreads();
    // ---- D[m][a] = sum_c S[m][c] * S[a][c] ----
    if (t < M2) {
        float s0 = Sfin[t * 3 + 0], s1 = Sfin[t * 3 + 1], s2 = Sfin[t * 3 + 2];
        float* o = out + (size_t)bid * (M2 * 4) + t * 4;
#pragma unroll
        for (int a = 0; a < 4; a++) {
            o[a] = s0 * Sfin[a * 3 + 0] + s1 * Sfin[a * 3 + 1] + s2 * Sfin[a * 3 + 2];
        }
    }
}

extern "C" void kernel_launch(void* const* d_in, const int* in_sizes, int n_in,
                              void* d_out, int out_size)
{
    const float* coords = (const float*)d_in[0];
    const int*   types  = (const int*)d_in[1];
    const float* W0     = (const float*)d_in[2];
    const float* b0     = (const float*)d_in[3];
    const float* W1     = (const float*)d_in[4];
    const float* b1     = (const float*)d_in[5];
    const float* W2     = (const float*)d_in[6];
    const float* b2     = (const float*)d_in[7];
    float* out = (float*)d_out;

    prep_kernel<<<1, NATOM>>>(types);
    main_kernel<<<NB * NATOM, TPB>>>(coords, types, W0, b0, W1, b1, W2, b2, out);
}